// round 11
// baseline (speedup 1.0000x reference)
#include <cuda_runtime.h>
#include <cuda_bf16.h>
#include <math.h>
#include <stdint.h>

typedef unsigned long long ull;

// ---------------------------------------------------------------------------
// Problem dimensions
// ---------------------------------------------------------------------------
#define B_   256
#define T_   256
#define DIN  256
#define H_   1024
#define FC_  512
#define DOUT 24
#define G4   4096
#define KTOT 1280        // H + DIN (fused [h | x_t] contraction)

// Balanced schedule: 296 CTAs = 2 per SM (148 SMs), pair sums 20-22 stage-units.
//   bids [0,76)    : gate SK4 chunks (10 stages)   tiles 0..37, slots 0..3
//   bids [76,116)  : gate SK2 chunks (20 stages)   tiles 38..57, slots 0..1
//   bids [116,148) : dec  SK2 chunks (16 stages)   tiles 0..15, slots 0..1
//   bids [148,224) : gate SK4 chunks (10 stages)   (second half of the 152)
//   bids [224,264) : gate SK20 chunks (2 stages)   tiles 58..59, slots 0..19
//   bids [264,296) : gate SK8 chunks (5 stages)    tiles 60..63, slots 0..7
#define NCTAS 296
#define MAXSLOT 20

#define ROWB 80                    // padded row stride in bytes (40 bf16)
#define REG_BYTES 10240            // 128 rows * 80B (one of Ahi/Alo/Bhi/Blo)
#define STG_BYTES 40960            // 4 regions per stage
#define SMEM_BYTES (2 * STG_BYTES) // double buffer: 80 KB dynamic

// ---------------------------------------------------------------------------
// Device scratch (static globals — no allocation allowed)
// ---------------------------------------------------------------------------
static __device__ __align__(16) __nv_bfloat16 g_WgT0[(size_t)G4 * KTOT];  // [n][k] hi
static __device__ __align__(16) __nv_bfloat16 g_WgT1[(size_t)G4 * KTOT];  // [n][k] lo
static __device__ __align__(16) __nv_bfloat16 g_WdT0[(size_t)H_ * H_];
static __device__ __align__(16) __nv_bfloat16 g_WdT1[(size_t)H_ * H_];
static __device__ __align__(16) __nv_bfloat16 g_xs0[(size_t)B_ * T_ * DIN];
static __device__ __align__(16) __nv_bfloat16 g_xs1[(size_t)B_ * T_ * DIN];
static __device__ __align__(16) __nv_bfloat16 g_hs0[(size_t)B_ * H_];
static __device__ __align__(16) __nv_bfloat16 g_hs1[(size_t)B_ * H_];
static __device__ __align__(16) __nv_bfloat16 g_cs0[(size_t)B_ * H_];
static __device__ __align__(16) __nv_bfloat16 g_cs1[(size_t)B_ * H_];
static __device__ float g_gateP[MAXSLOT][(size_t)B_ * G4];  // split-K partials
static __device__ float g_decP[2][(size_t)B_ * H_];
static __device__ float g_hf[(size_t)B_ * H_];          // fp32 hidden (in-place)
static __device__ float g_cf[(size_t)B_ * H_];          // fp32 cell (in-place)
static __device__ float g_ball[G4];                     // b_lin + b_extra
static __device__ float g_bd2[H_];                      // bd + b_decomp
static __device__ float g_tmp[(size_t)B_ * FC_];

// ---------------------------------------------------------------------------
// Helpers (baseline PTX only — compiles under .target sm_100)
// ---------------------------------------------------------------------------
__device__ __forceinline__ uint32_t smem_u32(const void* p) {
    uint32_t a;
    asm("{ .reg .u64 t; cvta.to.shared.u64 t, %1; cvt.u32.u64 %0, t; }"
        : "=r"(a) : "l"(p));
    return a;
}
__device__ __forceinline__ void cp16(uint32_t dst, const void* src) {
    asm volatile("cp.async.cg.shared.global [%0], [%1], 16;"
                 :: "r"(dst), "l"(src));
}
#define CP_COMMIT() asm volatile("cp.async.commit_group;")
#define CP_WAIT1()  asm volatile("cp.async.wait_group 1;")
#define CP_WAIT0()  asm volatile("cp.async.wait_group 0;")

__device__ __forceinline__ void ldsm4(uint32_t* r, uint32_t addr) {
    asm volatile("ldmatrix.sync.aligned.m8n8.x4.shared.b16 {%0,%1,%2,%3}, [%4];"
                 : "=r"(r[0]), "=r"(r[1]), "=r"(r[2]), "=r"(r[3]) : "r"(addr));
}
__device__ __forceinline__ void mma16816(float* c, const uint32_t* a,
                                         uint32_t b0, uint32_t b1) {
    asm volatile(
        "mma.sync.aligned.m16n8k16.row.col.f32.bf16.bf16.f32 "
        "{%0,%1,%2,%3}, {%4,%5,%6,%7}, {%8,%9}, {%0,%1,%2,%3};"
        : "+f"(c[0]), "+f"(c[1]), "+f"(c[2]), "+f"(c[3])
        : "r"(a[0]), "r"(a[1]), "r"(a[2]), "r"(a[3]), "r"(b0), "r"(b1));
}
__device__ __forceinline__ float sigm(float x) {
    return 1.0f / (1.0f + expf(-x));
}
__device__ __forceinline__ void bsplit(float v, __nv_bfloat16& hi, __nv_bfloat16& lo) {
    hi = __float2bfloat16(v);
    lo = __float2bfloat16(v - __bfloat162float(hi));
}

// ---------------------------------------------------------------------------
// One-time prep kernels
// ---------------------------------------------------------------------------
// transpose [K][N] -> [N][K] with bf16 hi/lo split; gate weights (Ux ‖ Wx)
__global__ void prep_wgate(const float* __restrict__ Ux, const float* __restrict__ Wx)
{
    __shared__ float tile[32][33];
    int tx = threadIdx.x, ty = threadIdx.y;
    int k0 = blockIdx.x * 32, n0 = blockIdx.y * 32;
#pragma unroll
    for (int i = 0; i < 4; i++) {
        int k = k0 + ty + i * 8, n = n0 + tx;
        tile[ty + i * 8][tx] = (k < H_) ? Ux[(size_t)k * G4 + n]
                                        : Wx[(size_t)(k - H_) * G4 + n];
    }
    __syncthreads();
#pragma unroll
    for (int i = 0; i < 4; i++) {
        int n = n0 + ty + i * 8, k = k0 + tx;
        float v = tile[tx][ty + i * 8];
        __nv_bfloat16 hi, lo; bsplit(v, hi, lo);
        g_WgT0[(size_t)n * KTOT + k] = hi;
        g_WgT1[(size_t)n * KTOT + k] = lo;
    }
}

__global__ void prep_wd(const float* __restrict__ Wd)
{
    __shared__ float tile[32][33];
    int tx = threadIdx.x, ty = threadIdx.y;
    int k0 = blockIdx.x * 32, n0 = blockIdx.y * 32;
#pragma unroll
    for (int i = 0; i < 4; i++)
        tile[ty + i * 8][tx] = Wd[(size_t)(k0 + ty + i * 8) * H_ + n0 + tx];
    __syncthreads();
#pragma unroll
    for (int i = 0; i < 4; i++) {
        int n = n0 + ty + i * 8, k = k0 + tx;
        float v = tile[tx][ty + i * 8];
        __nv_bfloat16 hi, lo; bsplit(v, hi, lo);
        g_WdT0[(size_t)n * H_ + k] = hi;
        g_WdT1[(size_t)n * H_ + k] = lo;
    }
}

// x split + all state/bias init merged (so step_mma(t=0) is launch #4)
__global__ __launch_bounds__(256) void prep_xinit(
    const float* __restrict__ x,
    const float* __restrict__ b_lin, const float* __restrict__ b_extra,
    const float* __restrict__ bd, const float* __restrict__ b_decomp)
{
    int gi = blockIdx.x * 256 + threadIdx.x;
    size_t i = (size_t)gi * 4;
    float4 v = *reinterpret_cast<const float4*>(&x[i]);
    __nv_bfloat16 h0, l0, h1, l1, h2, l2, h3, l3;
    bsplit(v.x, h0, l0); bsplit(v.y, h1, l1);
    bsplit(v.z, h2, l2); bsplit(v.w, h3, l3);
    __nv_bfloat162 a, b;
    a.x = h0; a.y = h1; b.x = h2; b.y = h3;
    *reinterpret_cast<__nv_bfloat162*>(&g_xs0[i])     = a;
    *reinterpret_cast<__nv_bfloat162*>(&g_xs0[i + 2]) = b;
    a.x = l0; a.y = l1; b.x = l2; b.y = l3;
    *reinterpret_cast<__nv_bfloat162*>(&g_xs1[i])     = a;
    *reinterpret_cast<__nv_bfloat162*>(&g_xs1[i + 2]) = b;

    if (gi < B_ * H_ / 4) {
        float4 z = make_float4(0.f, 0.f, 0.f, 0.f);
        *reinterpret_cast<float4*>(&g_hf[(size_t)gi * 4]) = z;
        *reinterpret_cast<float4*>(&g_cf[(size_t)gi * 4]) = z;
        reinterpret_cast<ull*>(g_hs0)[gi] = 0ULL;
        reinterpret_cast<ull*>(g_hs1)[gi] = 0ULL;
        reinterpret_cast<ull*>(g_cs0)[gi] = 0ULL;
        reinterpret_cast<ull*>(g_cs1)[gi] = 0ULL;
    }
    if (gi < G4 / 4) {
        float4 a4 = *reinterpret_cast<const float4*>(&b_lin[gi * 4]);
        float4 b4 = *reinterpret_cast<const float4*>(&b_extra[gi * 4]);
        *reinterpret_cast<float4*>(&g_ball[gi * 4]) =
            make_float4(a4.x + b4.x, a4.y + b4.y, a4.z + b4.z, a4.w + b4.w);
    }
    if (gi < H_ / 4) {
        float4 a4 = *reinterpret_cast<const float4*>(&bd[gi * 4]);
        float4 b4 = *reinterpret_cast<const float4*>(&b_decomp[gi * 4]);
        *reinterpret_cast<float4*>(&g_bd2[gi * 4]) =
            make_float4(a4.x + b4.x, a4.y + b4.y, a4.z + b4.z, a4.w + b4.w);
    }
}

// ---------------------------------------------------------------------------
// Per-step tensor-core GEMM via mma.sync (HMMA). 296 CTAs, 128 threads,
// 4 warps (2x2), warp tile 64x64. Variable-length split-K chunks scheduled
// so each SM's (bid, bid+148) pair sums to 20-22 k32-stage-units.
// 3-term bf16 split: Ahi*Bhi + Alo*Bhi + Ahi*Blo, fp32 accumulators.
// ---------------------------------------------------------------------------
__global__ __launch_bounds__(128) void step_mma(int t)
{
    extern __shared__ __align__(16) char smem[];
    const uint32_t sbase = smem_u32(smem);

    // ---- bid -> (isg, tile, kslot, nst) schedule ----
    const int bid = blockIdx.x;
    bool isg = true;
    int tile, kslot, nst;
    if (bid < 148) {
        if (bid < 76)       { tile = bid >> 2;             kslot = bid & 3;        nst = 10; }
        else if (bid < 116) { int j = bid - 76;  tile = 38 + (j >> 1); kslot = j & 1;  nst = 20; }
        else                { int j = bid - 116; isg = false; tile = j >> 1; kslot = j & 1; nst = 16; }
    } else {
        int j = bid - 148;
        if (j < 76)         { int idx = 76 + j;  tile = idx >> 2;       kslot = idx & 3; nst = 10; }
        else if (j < 116)   { int idx = j - 76;  tile = 58 + idx / 20;  kslot = idx % 20; nst = 2; }
        else                { int idx = j - 116; tile = 60 + (idx >> 3); kslot = idx & 7; nst = 5; }
    }
    const int m0 = (tile & 1) * 128;
    const int n0 = (tile >> 1) * 128;
    const int kbase = kslot * nst * 32;

    int bstride, ldO;
    const __nv_bfloat16 *Bhi, *Blo;
    float* Out;
    if (isg) {
        bstride = KTOT; ldO = G4;
        Bhi = g_WgT0; Blo = g_WgT1; Out = &g_gateP[kslot][0];
    } else {
        bstride = H_; ldO = H_;
        Bhi = g_WdT0; Blo = g_WdT1; Out = &g_decP[kslot][0];
    }
    const __nv_bfloat16* Ahi_s = isg ? g_hs0 : g_cs0;
    const __nv_bfloat16* Alo_s = isg ? g_hs1 : g_cs1;

    const int tid  = threadIdx.x;
    const int lane = tid & 31;
    const int warp = tid >> 5;
    const int wm   = (warp >> 1) * 64;
    const int wn   = (warp & 1) * 64;

    // ldmatrix per-lane byte offsets within a region
    uint32_t aoff[4], boff[4];
#pragma unroll
    for (int mt = 0; mt < 4; mt++)
        aoff[mt] = (uint32_t)((wm + mt * 16 + (lane & 15)) * ROWB +
                              ((lane >> 4) & 1) * 16);
#pragma unroll
    for (int np = 0; np < 4; np++)
        boff[np] = (uint32_t)((wn + np * 16 + (lane & 7) + ((lane >> 4) << 3)) * ROWB +
                              ((lane >> 3) & 1) * 16);

    float acc[4][8][4];
#pragma unroll
    for (int mt = 0; mt < 4; mt++)
#pragma unroll
        for (int nt = 0; nt < 8; nt++)
#pragma unroll
            for (int q = 0; q < 4; q++) acc[mt][nt][q] = 0.f;

    // ---- cp.async stage: Ahi|Alo|Bhi|Blo, 128 rows x 32 k bf16 each ----
    auto stage = [&](int s) {
        const uint32_t sb = sbase + (uint32_t)((s & 1) * STG_BYTES);
        const int k0 = kbase + s * 32;
#pragma unroll
        for (int j = 0; j < 16; j++) {
            const int idx = j * 128 + tid;
            const int w   = idx >> 9;           // region 0..3
            const int rem = idx & 511;
            const int rr  = rem >> 2;
            const int kc  = rem & 3;
            const int kg  = k0 + kc * 8;
            const __nv_bfloat16* src;
            if (w < 2) {
                if (isg && kg >= H_)
                    src = (w ? g_xs1 : g_xs0) +
                          ((size_t)(m0 + rr) * T_ + t) * DIN + (kg - H_);
                else
                    src = (w ? Alo_s : Ahi_s) + (size_t)(m0 + rr) * H_ + kg;
            } else {
                src = ((w == 2) ? Bhi : Blo) + (size_t)(n0 + rr) * bstride + kg;
            }
            cp16(sb + (uint32_t)(w * REG_BYTES + rr * ROWB + kc * 16), src);
        }
        CP_COMMIT();
    };

    stage(0);
    stage(1);
    CP_WAIT1();
    __syncthreads();

    for (int s = 0; ; s++) {
        const uint32_t sb = sbase + (uint32_t)((s & 1) * STG_BYTES);
#pragma unroll
        for (int kk = 0; kk < 2; kk++) {
            const uint32_t kb = sb + kk * 32;   // 16 bf16 = 32B per k16 step
            uint32_t ahif[4][4], alof[4][4], bfr[4][4];
#pragma unroll
            for (int mt = 0; mt < 4; mt++) {
                ldsm4(ahif[mt], kb + aoff[mt]);
                ldsm4(alof[mt], kb + REG_BYTES + aoff[mt]);
            }
#pragma unroll
            for (int np = 0; np < 4; np++)
                ldsm4(bfr[np], kb + 2 * REG_BYTES + boff[np]);
            // terms Ahi*Bhi and Alo*Bhi
#pragma unroll
            for (int mt = 0; mt < 4; mt++)
#pragma unroll
                for (int np = 0; np < 4; np++) {
                    mma16816(acc[mt][np * 2],     ahif[mt], bfr[np][0], bfr[np][1]);
                    mma16816(acc[mt][np * 2 + 1], ahif[mt], bfr[np][2], bfr[np][3]);
                    mma16816(acc[mt][np * 2],     alof[mt], bfr[np][0], bfr[np][1]);
                    mma16816(acc[mt][np * 2 + 1], alof[mt], bfr[np][2], bfr[np][3]);
                }
            // term Ahi*Blo (reuse bfr registers)
#pragma unroll
            for (int np = 0; np < 4; np++)
                ldsm4(bfr[np], kb + 3 * REG_BYTES + boff[np]);
#pragma unroll
            for (int mt = 0; mt < 4; mt++)
#pragma unroll
                for (int np = 0; np < 4; np++) {
                    mma16816(acc[mt][np * 2],     ahif[mt], bfr[np][0], bfr[np][1]);
                    mma16816(acc[mt][np * 2 + 1], ahif[mt], bfr[np][2], bfr[np][3]);
                }
        }
        if (s + 1 == nst) break;
        __syncthreads();                 // done reading buffer s&1
        if (s + 2 < nst) { stage(s + 2); CP_WAIT1(); }
        else             { CP_WAIT0(); }
        __syncthreads();                 // buffer (s+1)&1 fully staged
    }

    // ---- write split-K partial tile ----
    const int lr  = lane >> 2;
    const int lc2 = (lane & 3) * 2;
#pragma unroll
    for (int mt = 0; mt < 4; mt++) {
#pragma unroll
        for (int nt = 0; nt < 8; nt++) {
            const int row = m0 + wm + mt * 16 + lr;
            const int col = n0 + wn + nt * 8 + lc2;
            *reinterpret_cast<float2*>(&Out[(size_t)row * ldO + col]) =
                make_float2(acc[mt][nt][0], acc[mt][nt][1]);
            *reinterpret_cast<float2*>(&Out[(size_t)(row + 8) * ldO + col]) =
                make_float2(acc[mt][nt][2], acc[mt][nt][3]);
        }
    }
}

// ---------------------------------------------------------------------------
// Per-step epilogue: sum variable split-K partials (per-tile slot count),
// decay decomposition, LSTM gate math, emit bf16 hi/lo h and c.
// ---------------------------------------------------------------------------
__device__ __forceinline__ float4 sum_gate(int b, int col) {
    int nt = col >> 7;
    int skn = (nt < 19) ? 4 : (nt < 29) ? 2 : (nt == 29) ? 20 : 8;
    float4 r = make_float4(0.f, 0.f, 0.f, 0.f);
    for (int s = 0; s < skn; s++) {
        float4 a = *reinterpret_cast<const float4*>(
            &g_gateP[s][(size_t)b * G4 + col]);
        r.x += a.x; r.y += a.y; r.z += a.z; r.w += a.w;
    }
    return r;
}

__global__ __launch_bounds__(256) void step_epi(
    int t, const float* __restrict__ elapsed)   // [B][T]
{
    int idx = blockIdx.x * 256 + threadIdx.x;   // 0..65535
    int b = idx >> 8;
    int n4 = (idx & 255) << 2;

    float dt = elapsed[(size_t)b * T_ + t];
    float Td = 1.0f / logf(dt + 2.7183f);

    float4 gi = sum_gate(b, 0 * H_ + n4);
    float4 gf = sum_gate(b, 1 * H_ + n4);
    float4 go = sum_gate(b, 2 * H_ + n4);
    float4 gc = sum_gate(b, 3 * H_ + n4);

    float4 d0 = *reinterpret_cast<const float4*>(&g_decP[0][(size_t)b * H_ + n4]);
    float4 d1 = *reinterpret_cast<const float4*>(&g_decP[1][(size_t)b * H_ + n4]);
    float4 dec = make_float4(d0.x + d1.x, d0.y + d1.y, d0.z + d1.z, d0.w + d1.w);

    float4 bb  = *reinterpret_cast<const float4*>(&g_bd2[n4]);
    float4 cp4 = *reinterpret_cast<const float4*>(&g_cf[(size_t)b * H_ + n4]);
    float4 bi = *reinterpret_cast<const float4*>(&g_ball[0 * H_ + n4]);
    float4 bf = *reinterpret_cast<const float4*>(&g_ball[1 * H_ + n4]);
    float4 bo = *reinterpret_cast<const float4*>(&g_ball[2 * H_ + n4]);
    float4 bc = *reinterpret_cast<const float4*>(&g_ball[3 * H_ + n4]);

    float cn[4], hn[4];
#define TLSTM_COMP(K, X)                                                  \
    {                                                                     \
        float cst = tanhf(dec.X + bb.X);                                  \
        float cm = cp4.X - cst + Td * cst;                                \
        float c2 = sigm(gf.X + bf.X) * cm +                               \
                   sigm(gi.X + bi.X) * tanhf(gc.X + bc.X);                \
        cn[K] = c2;                                                       \
        hn[K] = sigm(go.X + bo.X) * tanhf(c2);                            \
    }
    TLSTM_COMP(0, x) TLSTM_COMP(1, y) TLSTM_COMP(2, z) TLSTM_COMP(3, w)
#undef TLSTM_COMP

    size_t o = (size_t)b * H_ + n4;
    *reinterpret_cast<float4*>(&g_cf[o]) = make_float4(cn[0], cn[1], cn[2], cn[3]);
    *reinterpret_cast<float4*>(&g_hf[o]) = make_float4(hn[0], hn[1], hn[2], hn[3]);

    __nv_bfloat16 chi[4], clo[4], hhi[4], hlo[4];
#pragma unroll
    for (int k = 0; k < 4; k++) {
        bsplit(cn[k], chi[k], clo[k]);
        bsplit(hn[k], hhi[k], hlo[k]);
    }
    __nv_bfloat162 p;
    p.x = chi[0]; p.y = chi[1]; *reinterpret_cast<__nv_bfloat162*>(&g_cs0[o])     = p;
    p.x = chi[2]; p.y = chi[3]; *reinterpret_cast<__nv_bfloat162*>(&g_cs0[o + 2]) = p;
    p.x = clo[0]; p.y = clo[1]; *reinterpret_cast<__nv_bfloat162*>(&g_cs1[o])     = p;
    p.x = clo[2]; p.y = clo[3]; *reinterpret_cast<__nv_bfloat162*>(&g_cs1[o + 2]) = p;
    p.x = hhi[0]; p.y = hhi[1]; *reinterpret_cast<__nv_bfloat162*>(&g_hs0[o])     = p;
    p.x = hhi[2]; p.y = hhi[3]; *reinterpret_cast<__nv_bfloat162*>(&g_hs0[o + 2]) = p;
    p.x = hlo[0]; p.y = hlo[1]; *reinterpret_cast<__nv_bfloat162*>(&g_hs1[o])     = p;
    p.x = hlo[2]; p.y = hlo[3]; *reinterpret_cast<__nv_bfloat162*>(&g_hs1[o + 2]) = p;
}

// ---------------------------------------------------------------------------
// Output head
// ---------------------------------------------------------------------------
__global__ __launch_bounds__(256) void fc1_kernel(
    const float* __restrict__ w, const float* __restrict__ bias)
{
    int idx = blockIdx.x * 256 + threadIdx.x;  // B*FC
    int b = idx >> 9, n = idx & 511;
    const float* hrow = &g_hf[(size_t)b * H_];
    float acc = bias[n];
#pragma unroll 8
    for (int k = 0; k < H_; k++)
        acc += hrow[k] * w[(size_t)k * FC_ + n];
    g_tmp[idx] = fmaxf(acc, 0.0f);
}

__global__ __launch_bounds__(256) void fco_kernel(
    const float* __restrict__ w, const float* __restrict__ bias,
    float* __restrict__ out)
{
    int idx = blockIdx.x * 256 + threadIdx.x;  // B*DOUT
    if (idx >= B_ * DOUT) return;
    int b = idx / DOUT, n = idx % DOUT;
    const float* trow = &g_tmp[(size_t)b * FC_];
    float acc = bias[n];
#pragma unroll 8
    for (int k = 0; k < FC_; k++)
        acc += trow[k] * w[(size_t)k * DOUT + n];
    out[idx] = acc;
}

// ---------------------------------------------------------------------------
// Launch
// ---------------------------------------------------------------------------
extern "C" void kernel_launch(void* const* d_in, const int* in_sizes, int n_in,
                              void* d_out, int out_size) {
    (void)in_sizes; (void)n_in; (void)out_size;
    const float* x        = (const float*)d_in[0];
    const float* elapsed  = (const float*)d_in[1];
    const float* Wx       = (const float*)d_in[2];
    const float* Ux       = (const float*)d_in[3];
    const float* b_lin    = (const float*)d_in[4];
    const float* b_extra  = (const float*)d_in[5];
    const float* Wd       = (const float*)d_in[6];
    const float* bd       = (const float*)d_in[7];
    const float* b_decomp = (const float*)d_in[8];
    const float* fc1_w    = (const float*)d_in[9];
    const float* fc1_b    = (const float*)d_in[10];
    const float* fco_w    = (const float*)d_in[11];
    const float* fco_b    = (const float*)d_in[12];
    float* out = (float*)d_out;

    static int smem_set = 0;
    if (!smem_set) {
        cudaFuncSetAttribute(step_mma,
                             cudaFuncAttributeMaxDynamicSharedMemorySize,
                             SMEM_BYTES);
        smem_set = 1;
    }

    // one-time prep (inside graph; deterministic per call)
    prep_wgate<<<dim3(KTOT / 32, G4 / 32), dim3(32, 8)>>>(Ux, Wx);
    prep_wd<<<dim3(H_ / 32, H_ / 32), dim3(32, 8)>>>(Wd);
    prep_xinit<<<(B_ * T_ * DIN / 4) / 256, 256>>>(x, b_lin, b_extra, bd, b_decomp);

    // sequential recurrence: balanced 296-CTA HMMA GEMM + epilogue per step
    for (int t = 0; t < T_; t++) {
        step_mma<<<NCTAS, 128, SMEM_BYTES>>>(t);
        step_epi<<<256, 256>>>(t, elapsed);
    }

    fc1_kernel<<<(B_ * FC_) / 256, 256>>>(fc1_w, fc1_b);
    fco_kernel<<<(B_ * DOUT + 255) / 256, 256>>>(fco_w, fco_b, out);
}